// round 14
// baseline (speedup 1.0000x reference)
#include <cuda_runtime.h>
#include <cuda_bf16.h>
#include <math.h>

// ---------------- problem constants ----------------
#define B_       2
#define NQ_      1600
#define D_       256
#define H_       8
#define HD_      32
#define DFFN_    1024
#define STOT_    5440
#define MROWS_   (B_*NQ_)          // 3200
#define MSRC_    (B_*STOT_)        // 10880
#define XSZ_     (MROWS_*D_)       // 819200
#define NLAYERS_ 6
#define VCOLS_   (NLAYERS_*D_)     // 1536

// ---------------- device scratch (static, no allocation) ----------------
__device__ float g_x    [XSZ_];
__device__ float g_qkv  [MROWS_*768];
__device__ float g_t    [XSZ_];
__device__ float g_t2   [4*XSZ_];          // up to 4 split-K partials
__device__ float g_offaw[2*MROWS_*384];    // 2 split-K partials
__device__ float g_val6 [MSRC_*VCOLS_];
__device__ float g_ffn  [MROWS_*DFFN_];

// ---------------- f32x2 packed-math helpers (sm_100+) ----------------
__device__ __forceinline__ unsigned long long pack2(float x) {
    unsigned long long r;
    unsigned int u = __float_as_uint(x);
    asm("mov.b64 %0, {%1, %1};" : "=l"(r) : "r"(u));
    return r;
}
__device__ __forceinline__ void fma2(unsigned long long& d, unsigned long long a, unsigned long long b) {
    asm("fma.rn.f32x2 %0, %1, %2, %0;" : "+l"(d) : "l"(a), "l"(b));
}
__device__ __forceinline__ void mul2(unsigned long long& d, unsigned long long a) {
    asm("mul.rn.f32x2 %0, %0, %1;" : "+l"(d) : "l"(a));
}
__device__ __forceinline__ void add2(unsigned long long& d, unsigned long long a) {
    asm("add.rn.f32x2 %0, %0, %1;" : "+l"(d) : "l"(a));
}
__device__ __forceinline__ float2 unpack2(unsigned long long v) {
    unsigned int lo, hi;
    asm("mov.b64 {%0, %1}, %2;" : "=r"(lo), "=r"(hi) : "l"(v));
    return make_float2(__uint_as_float(lo), __uint_as_float(hi));
}

// ---------------- GEMM: Cpart[z][M,N] = (A (+A2 on n<NADD)) * Wseg^T (+bias on z==0) ----
// W values stored in smem PRE-DUPLICATED as float2{w,w} so the FFMA2 broadcast
// operand comes straight from LDS.128 (no pack MOVs in the inner loop).
// Tile 128x64, 256 threads, BK=16, FFMA2 8x4 micro-tile.
template<bool RELU, bool ADD, int SPLITK>
__launch_bounds__(256)
__global__ void gemm4_kernel(const float* __restrict__ A, const float* __restrict__ A2, int NADD,
                             const float* __restrict__ W1, const float* __restrict__ b1, int s1,
                             const float* __restrict__ W2, const float* __restrict__ b2, int s2,
                             const float* __restrict__ W3, const float* __restrict__ b3,
                             float* __restrict__ C, int M, int N, int Kt, int Ks) {
    __shared__ float As[2][16][128];
    __shared__ __align__(16) float2 Wsp[2][16][66];  // 66-pad: rows 528B (16B-aligned cols, bank shift 4)
    const int tid = threadIdx.x;
    const int tx = tid & 15, ty = tid >> 4;
    const int m0 = blockIdx.y * 128, n0 = blockIdx.x * 64;
    const int kbase = (SPLITK > 1) ? (int)blockIdx.z * Ks : 0;

    const float* Wb; const float* bb; int nW;
    if (n0 < s1)      { Wb = W1; bb = b1; nW = n0; }
    else if (n0 < s2) { Wb = W2; bb = b2; nW = n0 - s1; }
    else              { Wb = W3; bb = b3; nW = n0 - s2; }

    const bool useAdd = ADD && (n0 < NADD);

    unsigned long long acc[4][4];
    #pragma unroll
    for (int i = 0; i < 4; i++)
        #pragma unroll
        for (int j = 0; j < 4; j++) acc[i][j] = 0ull;

    const int r = tid >> 2, f = tid & 3;
    const float* Ap0 = A + (size_t)(m0 + r) * Kt + kbase + f * 4;
    const float* Ap1 = Ap0 + (size_t)64 * Kt;
    const float* A2p0 = nullptr; const float* A2p1 = nullptr;
    if (ADD) {
        A2p0 = A2 + (size_t)(m0 + r) * Kt + kbase + f * 4;
        A2p1 = A2p0 + (size_t)64 * Kt;
    }
    const float* Wp = Wb + (size_t)(nW + r) * Kt + kbase + f * 4;

    float4 a0, a1, w0;
    auto ldg = [&](int ko) {
        a0 = *(const float4*)(Ap0 + ko);
        a1 = *(const float4*)(Ap1 + ko);
        if (ADD && useAdd) {
            float4 e0 = *(const float4*)(A2p0 + ko);
            float4 e1 = *(const float4*)(A2p1 + ko);
            a0.x += e0.x; a0.y += e0.y; a0.z += e0.z; a0.w += e0.w;
            a1.x += e1.x; a1.y += e1.y; a1.z += e1.z; a1.w += e1.w;
        }
        w0 = *(const float4*)(Wp + ko);
    };
    auto stage = [&](int buf) {
        const int k4 = f * 4, sw = f << 3;
        As[buf][k4+0][r ^ sw] = a0.x; As[buf][k4+1][r ^ sw] = a0.y;
        As[buf][k4+2][r ^ sw] = a0.z; As[buf][k4+3][r ^ sw] = a0.w;
        As[buf][k4+0][(r+64) ^ sw] = a1.x; As[buf][k4+1][(r+64) ^ sw] = a1.y;
        As[buf][k4+2][(r+64) ^ sw] = a1.z; As[buf][k4+3][(r+64) ^ sw] = a1.w;
        Wsp[buf][k4+0][r] = make_float2(w0.x, w0.x);
        Wsp[buf][k4+1][r] = make_float2(w0.y, w0.y);
        Wsp[buf][k4+2][r] = make_float2(w0.z, w0.z);
        Wsp[buf][k4+3][r] = make_float2(w0.w, w0.w);
    };

    ldg(0);
    stage(0);
    __syncthreads();

    const int nit = Ks >> 4;
    const int ty8 = ty * 8, tx4 = tx * 4;
    for (int it = 0; it < nit; ++it) {
        const int buf = it & 1;
        if (it + 1 < nit) ldg((it + 1) << 4);
        #pragma unroll
        for (int k = 0; k < 16; k++) {
            const int sk = ((k >> 2) & 3) << 3;
            const float* ap = &As[buf][k][ty8 ^ sk];
            ulonglong2 aA = *(const ulonglong2*)ap;
            ulonglong2 aB = *(const ulonglong2*)(ap + 4);
            const ulonglong2 w01 = *(const ulonglong2*)&Wsp[buf][k][tx4];
            const ulonglong2 w23 = *(const ulonglong2*)&Wsp[buf][k][tx4 + 2];
            fma2(acc[0][0], aA.x, w01.x); fma2(acc[0][1], aA.x, w01.y);
            fma2(acc[0][2], aA.x, w23.x); fma2(acc[0][3], aA.x, w23.y);
            fma2(acc[1][0], aA.y, w01.x); fma2(acc[1][1], aA.y, w01.y);
            fma2(acc[1][2], aA.y, w23.x); fma2(acc[1][3], aA.y, w23.y);
            fma2(acc[2][0], aB.x, w01.x); fma2(acc[2][1], aB.x, w01.y);
            fma2(acc[2][2], aB.x, w23.x); fma2(acc[2][3], aB.x, w23.y);
            fma2(acc[3][0], aB.y, w01.x); fma2(acc[3][1], aB.y, w01.y);
            fma2(acc[3][2], aB.y, w23.x); fma2(acc[3][3], aB.y, w23.y);
        }
        if (it + 1 < nit) stage(buf ^ 1);
        __syncthreads();
    }

    float bv[4] = {0.f, 0.f, 0.f, 0.f};
    if (SPLITK == 1 || blockIdx.z == 0) {
        const float4 bb4 = *(const float4*)&bb[nW + tx4];
        bv[0] = bb4.x; bv[1] = bb4.y; bv[2] = bb4.z; bv[3] = bb4.w;
    }
    float* Cz = C + (SPLITK > 1 ? (size_t)blockIdx.z * M * N : 0);
    #pragma unroll
    for (int j = 0; j < 4; j++) {
        const int n = n0 + tx4 + j;
        #pragma unroll
        for (int i = 0; i < 4; i++) {
            float2 v = unpack2(acc[i][j]);
            float o0 = v.x + bv[j], o1 = v.y + bv[j];
            if (RELU) { o0 = fmaxf(o0, 0.f); o1 = fmaxf(o1, 0.f); }
            const int m = m0 + ty8 + i * 2;
            Cz[(size_t)m * N + n]       = o0;
            Cz[(size_t)(m + 1) * N + n] = o1;
        }
    }
}

// ---------------- fused self-attention (flash, FFMA2, 2 queries/thread) ----------------
// qkv layout: [B*NQ, 768]: Q cols 0..255, K cols 256..511, V cols 512..767.
// grid = (NQ/32, H, B), block = 128.
__launch_bounds__(128)
__global__ void attn3_kernel(const float* __restrict__ qkv, float* __restrict__ out) {
    __shared__ float Ks[64][36];
    __shared__ float Vs[64][36];
    const int qt = blockIdx.x, h = blockIdx.y, b = blockIdx.z;
    const int tid = threadIdx.x;
    const int ql = tid >> 3, sub = tid & 7;
    const size_t qb = (size_t)b * NQ_ * 768 + h * HD_;
    const size_t ob = (size_t)b * NQ_ * D_ + h * HD_;
    const int qA = qt * 32 + ql;
    const int qB = qA + 16;
    const float* qrowA = qkv + qb + (size_t)qA * 768;
    const float* qrowB = qkv + qb + (size_t)qB * 768;

    unsigned long long q2a[16], q2b[16];
    #pragma unroll
    for (int p = 0; p < 8; p++) {
        ulonglong2 ta = *(const ulonglong2*)(qrowA + p * 4);
        ulonglong2 tb = *(const ulonglong2*)(qrowB + p * 4);
        q2a[2*p] = ta.x; q2a[2*p+1] = ta.y;
        q2b[2*p] = tb.x; q2b[2*p+1] = tb.y;
    }
    unsigned long long o2a[16], o2b[16];
    #pragma unroll
    for (int p = 0; p < 16; p++) { o2a[p] = 0ull; o2b[p] = 0ull; }

    const float scale = 0.17677669529663687f; // 1/sqrt(32)
    float mA = -1e30f, lA = 0.f;
    float mB = -1e30f, lB = 0.f;

    for (int kt = 0; kt < NQ_ / 64; kt++) {
        __syncthreads();
        #pragma unroll
        for (int i = 0; i < 4; i++) {
            int e = tid + i * 128;
            int kr = e >> 3, dc = (e & 7) * 4;
            const float* base = qkv + qb + (size_t)(kt * 64 + kr) * 768;
            *(float4*)&Ks[kr][dc] = *(const float4*)(base + 256 + dc);
            *(float4*)&Vs[kr][dc] = *(const float4*)(base + 512 + dc);
        }
        __syncthreads();

        float sA[8], sB[8];
        #pragma unroll
        for (int j = 0; j < 8; j++) {
            const float* kp = &Ks[j * 8 + sub][0];
            unsigned long long c0a = 0ull, c1a = 0ull, c0b = 0ull, c1b = 0ull;
            #pragma unroll
            for (int p = 0; p < 8; p++) {
                ulonglong2 kk = *(const ulonglong2*)(kp + p * 4);
                fma2(c0a, q2a[2*p],   kk.x);
                fma2(c1a, q2a[2*p+1], kk.y);
                fma2(c0b, q2b[2*p],   kk.x);
                fma2(c1b, q2b[2*p+1], kk.y);
            }
            float2 r0 = unpack2(c0a), r1 = unpack2(c1a);
            sA[j] = ((r0.x + r0.y) + (r1.x + r1.y)) * scale;
            float2 r2 = unpack2(c0b), r3 = unpack2(c1b);
            sB[j] = ((r2.x + r2.y) + (r3.x + r3.y)) * scale;
        }
        float tA = sA[0], tB = sB[0];
        #pragma unroll
        for (int j = 1; j < 8; j++) { tA = fmaxf(tA, sA[j]); tB = fmaxf(tB, sB[j]); }
        #pragma unroll
        for (int st = 1; st < 8; st <<= 1) {
            tA = fmaxf(tA, __shfl_xor_sync(0xffffffffu, tA, st));
            tB = fmaxf(tB, __shfl_xor_sync(0xffffffffu, tB, st));
        }

        const float mnA = fmaxf(mA, tA);
        const float crA = __expf(mA - mnA);
        mA = mnA; lA *= crA;
        const float mnB = fmaxf(mB, tB);
        const float crB = __expf(mB - mnB);
        mB = mnB; lB *= crB;
        const unsigned long long c2a = pack2(crA), c2b = pack2(crB);
        #pragma unroll
        for (int p = 0; p < 16; p++) { mul2(o2a[p], c2a); mul2(o2b[p], c2b); }

        float eA[8], eB[8];
        #pragma unroll
        for (int j = 0; j < 8; j++) {
            eA[j] = __expf(sA[j] - mA); lA += eA[j];
            eB[j] = __expf(sB[j] - mB); lB += eB[j];
        }
        #pragma unroll
        for (int j = 0; j < 8; j++) {
            const unsigned long long e2a = pack2(eA[j]);
            const unsigned long long e2b = pack2(eB[j]);
            const float* vp = &Vs[j * 8 + sub][0];
            #pragma unroll
            for (int p = 0; p < 8; p++) {
                ulonglong2 vv = *(const ulonglong2*)(vp + p * 4);
                fma2(o2a[2*p],   e2a, vv.x);
                fma2(o2a[2*p+1], e2a, vv.y);
                fma2(o2b[2*p],   e2b, vv.x);
                fma2(o2b[2*p+1], e2b, vv.y);
            }
        }
    }

    #pragma unroll
    for (int st = 1; st < 8; st <<= 1) {
        lA += __shfl_xor_sync(0xffffffffu, lA, st);
        lB += __shfl_xor_sync(0xffffffffu, lB, st);
        #pragma unroll
        for (int p = 0; p < 16; p++) {
            unsigned long long oa = __shfl_xor_sync(0xffffffffu, o2a[p], st);
            add2(o2a[p], oa);
            unsigned long long obv = __shfl_xor_sync(0xffffffffu, o2b[p], st);
            add2(o2b[p], obv);
        }
    }
    const unsigned long long iA = pack2(1.f / lA);
    const unsigned long long iB = pack2(1.f / lB);
    unsigned long long a0 = o2a[sub * 2], a1 = o2a[sub * 2 + 1];
    unsigned long long b0 = o2b[sub * 2], b1 = o2b[sub * 2 + 1];
    mul2(a0, iA); mul2(a1, iA);
    mul2(b0, iB); mul2(b1, iB);
    float2 ra0 = unpack2(a0), ra1 = unpack2(a1);
    float2 rb0 = unpack2(b0), rb1 = unpack2(b1);
    *(float4*)(out + ob + (size_t)qA * D_ + sub * 4) = make_float4(ra0.x, ra0.y, ra1.x, ra1.y);
    *(float4*)(out + ob + (size_t)qB * D_ + sub * 4) = make_float4(rb0.x, rb0.y, rb1.x, rb1.y);
}

// ---------------- MS deformable sampling (fused 16-wide softmax; 2 offaw partials) ----
// grid = B*NQ, block = 256 (thread = h*32 + hd). val6: [MSRC, 1536], layer slice at col l*256.
__global__ void msda_kernel(const float* __restrict__ val6, const float* __restrict__ offaw,
                            const float* __restrict__ refp, float* __restrict__ out, int l) {
    __shared__ float aw_s[128];
    const int bq = blockIdx.x;
    const int b = bq / NQ_;
    const int tid = threadIdx.x;
    const float* off0 = offaw + (size_t)bq * 384;
    const float* off1 = off0 + (size_t)MROWS_ * 384;

    // fused softmax over each head's 16 logits (threads 0..127; 16-lane shfl groups)
    if (tid < 128) {
        float v = off0[256 + tid] + off1[256 + tid];
        float mx = v;
        #pragma unroll
        for (int st = 1; st < 16; st <<= 1)
            mx = fmaxf(mx, __shfl_xor_sync(0xffffffffu, mx, st));
        const float e = __expf(v - mx);
        float s = e;
        #pragma unroll
        for (int st = 1; st < 16; st <<= 1)
            s += __shfl_xor_sync(0xffffffffu, s, st);
        aw_s[tid] = e / s;
    }
    __syncthreads();

    const int h = tid >> 5;
    const int hd = tid & 31;
    const float* rr = refp + (size_t)bq * 8;
    const float* vb = val6 + (size_t)b * STOT_ * VCOLS_ + l * D_ + h * HD_ + hd;
    float acc = 0.f;
    const int LVL_W[4]  = {64, 32, 16, 8};
    const int LVL_S0[4] = {0, 4096, 5120, 5376};
    #pragma unroll
    for (int lv = 0; lv < 4; lv++) {
        const int Wl = LVL_W[lv];
        const float Wf = (float)Wl;
        const int s0 = LVL_S0[lv];
        const float rx = rr[lv*2 + 0];
        const float ry = rr[lv*2 + 1];
        #pragma unroll
        for (int p = 0; p < 4; p++) {
            const int oi = (((h*4 + lv)*4) + p) * 2;
            const float ox = off0[oi + 0] + off1[oi + 0];
            const float oy = off0[oi + 1] + off1[oi + 1];
            const float locx = rx + ox / Wf;
            const float locy = ry + oy / Wf;   // H == W per level
            const float xx = locx * Wf - 0.5f;
            const float yy = locy * Wf - 0.5f;
            const float x0 = floorf(xx), y0 = floorf(yy);
            const float wx1 = xx - x0, wy1 = yy - y0;
            float sampv = 0.f;
            #pragma unroll
            for (int dy = 0; dy < 2; dy++) {
                const float yi = y0 + (float)dy;
                const float wy = dy ? wy1 : (1.f - wy1);
                #pragma unroll
                for (int dx = 0; dx < 2; dx++) {
                    const float xi = x0 + (float)dx;
                    const float wx = dx ? wx1 : (1.f - wx1);
                    const bool valid = (xi >= 0.f) && (xi <= Wf - 1.f) &&
                                       (yi >= 0.f) && (yi <= Wf - 1.f);
                    const float w = wx * wy * (valid ? 1.f : 0.f);
                    if (w != 0.f) {
                        const int xic = (int)fminf(fmaxf(xi, 0.f), Wf - 1.f);
                        const int yic = (int)fminf(fmaxf(yi, 0.f), Wf - 1.f);
                        const float g = vb[(size_t)(s0 + yic * Wl + xic) * VCOLS_];
                        sampv += g * w;
                    }
                }
            }
            acc += sampv * aw_s[h*16 + lv*4 + p];
        }
    }
    out[(size_t)bq * D_ + tid] = acc;
}

// ---------------- residual + layernorm: dst = LN(a + sum of NPART partials) ----------------
template<int NPART>
__global__ void ln_kernel(float* __restrict__ dst, const float* __restrict__ a,
                          const float* __restrict__ parts, const float* __restrict__ g,
                          const float* __restrict__ beta) {
    const int row = blockIdx.x;
    const int c = threadIdx.x;
    const size_t idx = (size_t)row * D_ + c;
    float v = a[idx];
    #pragma unroll
    for (int p = 0; p < NPART; p++) v += parts[(size_t)p * XSZ_ + idx];
    __shared__ float red[8];
    __shared__ float sh_mu, sh_var;
    float s = v;
    #pragma unroll
    for (int o = 16; o; o >>= 1) s += __shfl_xor_sync(0xffffffffu, s, o);
    if ((c & 31) == 0) red[c >> 5] = s;
    __syncthreads();
    if (c == 0) {
        float t = 0.f;
        #pragma unroll
        for (int i = 0; i < 8; i++) t += red[i];
        sh_mu = t * (1.f / 256.f);
    }
    __syncthreads();
    const float mu = sh_mu;
    const float d = v - mu;
    s = d * d;
    #pragma unroll
    for (int o = 16; o; o >>= 1) s += __shfl_xor_sync(0xffffffffu, s, o);
    if ((c & 31) == 0) red[c >> 5] = s;
    __syncthreads();
    if (c == 0) {
        float t = 0.f;
        #pragma unroll
        for (int i = 0; i < 8; i++) t += red[i];
        sh_var = t * (1.f / 256.f);
    }
    __syncthreads();
    const float y = d * rsqrtf(sh_var + 1e-5f) * g[c] + beta[c];
    dst[idx] = y;
}

// ---------------- host orchestration ----------------
extern "C" void kernel_launch(void* const* d_in, const int* in_sizes, int n_in,
                              void* d_out, int out_size) {
    (void)in_sizes; (void)n_in; (void)out_size;
    const float* tgt      = (const float*)d_in[0];
    const float* qpos     = (const float*)d_in[1];
    const float* refp     = (const float*)d_in[2];
    const float* src      = (const float*)d_in[3];
    const float* sa_w_q   = (const float*)d_in[4];
    const float* sa_b_q   = (const float*)d_in[5];
    const float* sa_w_k   = (const float*)d_in[6];
    const float* sa_b_k   = (const float*)d_in[7];
    const float* sa_w_v   = (const float*)d_in[8];
    const float* sa_b_v   = (const float*)d_in[9];
    const float* sa_w_o   = (const float*)d_in[10];
    const float* sa_b_o   = (const float*)d_in[11];
    const float* ln2_g    = (const float*)d_in[12];
    const float* ln2_b    = (const float*)d_in[13];
    const float* ca_w_off = (const float*)d_in[14];
    const float* ca_b_off = (const float*)d_in[15];
    const float* ca_w_attn= (const float*)d_in[16];
    const float* ca_b_attn= (const float*)d_in[17];
    const float* ca_w_val = (const float*)d_in[18];
    const float* ca_b_val = (const float*)d_in[19];
    const float* ca_w_out = (const float*)d_in[20];
    const float* ca_b_out = (const float*)d_in[21];
    const float* ln1_g    = (const float*)d_in[22];
    const float* ln1_b    = (const float*)d_in[23];
    const float* ffn_w1   = (const float*)d_in[24];
    const float* ffn_b1   = (const float*)d_in[25];
    const float* ffn_w2   = (const float*)d_in[26];
    const float* ffn_b2   = (const float*)d_in[27];
    const float* ln3_g    = (const float*)d_in[28];
    const float* ln3_b    = (const float*)d_in[29];

    float *x, *qkv, *t, *t2, *offaw, *val6, *ffn;
    cudaGetSymbolAddress((void**)&x,     g_x);
    cudaGetSymbolAddress((void**)&qkv,   g_qkv);
    cudaGetSymbolAddress((void**)&t,     g_t);
    cudaGetSymbolAddress((void**)&t2,    g_t2);
    cudaGetSymbolAddress((void**)&offaw, g_offaw);
    cudaGetSymbolAddress((void**)&val6,  g_val6);
    cudaGetSymbolAddress((void**)&ffn,   g_ffn);

    // one big value projection for all 6 layers: val6 = src @ ca_w_val^T + b  (N=1536)
    gemm4_kernel<false, false, 1><<<dim3(VCOLS_/64, MSRC_/128), 256>>>(
        src, nullptr, 0,
        ca_w_val, ca_b_val, VCOLS_, ca_w_val, ca_b_val, VCOLS_, ca_w_val, ca_b_val,
        val6, MSRC_, VCOLS_, D_, D_);

    const dim3 GQKV (768/64,   MROWS_/128);     // (12, 25) = 300 CTAs
    const dim3 GPROJ(D_/64,    MROWS_/128, 4);  // (4, 25, 4) = 400 CTAs, split-K4
    const dim3 GOA  (384/64,   MROWS_/128, 2);  // (6, 25, 2) = 300 CTAs, split-K2
    const dim3 GF1  (DFFN_/64, MROWS_/128);     // (16, 25) = 400 CTAs
    const dim3 GF2  (D_/64,    MROWS_/128, 4);  // (4, 25, 4) = 400 CTAs, split-K4
    const dim3 GATTN(NQ_/32, H_, B_);           // (50, 8, 2) = 800 CTAs

    for (int i = 0; i < NLAYERS_; i++) {
        const float* wq = sa_w_q + (size_t)i*D_*D_;   const float* bq = sa_b_q + i*D_;
        const float* wk = sa_w_k + (size_t)i*D_*D_;   const float* bk = sa_b_k + i*D_;
        const float* wv = sa_w_v + (size_t)i*D_*D_;   const float* bv = sa_b_v + i*D_;
        const float* wo = sa_w_o + (size_t)i*D_*D_;   const float* bo = sa_b_o + i*D_;
        const float* woff = ca_w_off + (size_t)i*D_*D_;     const float* boff = ca_b_off + i*D_;
        const float* watt = ca_w_attn + (size_t)i*128*D_;   const float* batt = ca_b_attn + i*128;
        const float* wco  = ca_w_out + (size_t)i*D_*D_;     const float* bco  = ca_b_out + i*D_;
        const float* w1 = ffn_w1 + (size_t)i*DFFN_*D_;      const float* b1 = ffn_b1 + i*DFFN_;
        const float* w2 = ffn_w2 + (size_t)i*D_*DFFN_;      const float* b2 = ffn_b2 + i*D_;

        const float* xin = (i == 0) ? tgt : x;

        // ---- self attention ----
        gemm4_kernel<false, true, 1><<<GQKV, 256>>>(
            xin, qpos, 512,
            wq, bq, 256, wk, bk, 512, wv, bv,
            qkv, MROWS_, 768, D_, D_);
        attn3_kernel<<<GATTN, 128>>>(qkv, t);
        gemm4_kernel<false, false, 4><<<GPROJ, 256>>>(
            t, nullptr, 0,
            wo, bo, 256, wo, bo, 256, wo, bo,
            t2, MROWS_, D_, D_, D_/4);
        ln_kernel<4><<<MROWS_, 256>>>(x, xin, t2, ln2_g + i*D_, ln2_b + i*D_);

        // ---- deformable cross attention ----
        gemm4_kernel<false, true, 2><<<GOA, 256>>>(
            x, qpos, 384,
            woff, boff, 256, watt, batt, 384, watt, batt,
            offaw, MROWS_, 384, D_, D_/2);
        msda_kernel<<<MROWS_, 256>>>(val6, offaw, refp, t, i);
        gemm4_kernel<false, false, 4><<<GPROJ, 256>>>(
            t, nullptr, 0,
            wco, bco, 256, wco, bco, 256, wco, bco,
            t2, MROWS_, D_, D_, D_/4);
        ln_kernel<4><<<MROWS_, 256>>>(x, x, t2, ln1_g + i*D_, ln1_b + i*D_);

        // ---- FFN ----
        gemm4_kernel<true, false, 1><<<GF1, 256>>>(
            x, nullptr, 0,
            w1, b1, DFFN_, w1, b1, DFFN_, w1, b1,
            ffn, MROWS_, DFFN_, D_, D_);
        gemm4_kernel<false, false, 4><<<GF2, 256>>>(
            ffn, nullptr, 0,
            w2, b2, 256, w2, b2, 256, w2, b2,
            t2, MROWS_, D_, DFFN_, DFFN_/4);
        float* dst = (i == NLAYERS_ - 1) ? (float*)d_out : x;
        ln_kernel<4><<<MROWS_, 256>>>(dst, x, t2, ln3_g + i*D_, ln3_b + i*D_);
    }
}

// round 15
// speedup vs baseline: 1.2117x; 1.2117x over previous
#include <cuda_runtime.h>
#include <cuda_bf16.h>
#include <math.h>

// ---------------- problem constants ----------------
#define B_       2
#define NQ_      1600
#define D_       256
#define H_       8
#define HD_      32
#define DFFN_    1024
#define STOT_    5440
#define MROWS_   (B_*NQ_)          // 3200
#define MSRC_    (B_*STOT_)        // 10880
#define XSZ_     (MROWS_*D_)       // 819200
#define NLAYERS_ 6
#define VCOLS_   (NLAYERS_*D_)     // 1536

// ---------------- device scratch (static, no allocation) ----------------
__device__ float g_x    [XSZ_];
__device__ float g_qkv  [MROWS_*768];
__device__ float g_t    [XSZ_];
__device__ float g_t2   [8*XSZ_];          // up to 8 split-K partials
__device__ float g_offaw[4*MROWS_*384];    // up to 4 split-K partials
__device__ float g_val6 [MSRC_*VCOLS_];
__device__ float g_ffn  [MROWS_*DFFN_];

// ---------------- f32x2 packed-math helpers (sm_100+) ----------------
__device__ __forceinline__ unsigned long long pack2(float x) {
    unsigned long long r;
    unsigned int u = __float_as_uint(x);
    asm("mov.b64 %0, {%1, %1};" : "=l"(r) : "r"(u));
    return r;
}
__device__ __forceinline__ void fma2(unsigned long long& d, unsigned long long a, unsigned long long b) {
    asm("fma.rn.f32x2 %0, %1, %2, %0;" : "+l"(d) : "l"(a), "l"(b));
}
__device__ __forceinline__ void mul2(unsigned long long& d, unsigned long long a) {
    asm("mul.rn.f32x2 %0, %0, %1;" : "+l"(d) : "l"(a));
}
__device__ __forceinline__ void add2(unsigned long long& d, unsigned long long a) {
    asm("add.rn.f32x2 %0, %0, %1;" : "+l"(d) : "l"(a));
}
__device__ __forceinline__ float2 unpack2(unsigned long long v) {
    unsigned int lo, hi;
    asm("mov.b64 {%0, %1}, %2;" : "=r"(lo), "=r"(hi) : "l"(v));
    return make_float2(__uint_as_float(lo), __uint_as_float(hi));
}

// ---------------- GEMM: Cpart[z][M,N] = (A (+A2 on n<NADD)) * Wseg^T (+bias on z==0) ----
// Round-13 proven version: Ws plain floats, pack2 in inner loop.
// Tile 128x64, 256 threads, BK=16, FFMA2 8x4 micro-tile.
template<bool RELU, bool ADD, int SPLITK>
__launch_bounds__(256)
__global__ void gemm4_kernel(const float* __restrict__ A, const float* __restrict__ A2, int NADD,
                             const float* __restrict__ W1, const float* __restrict__ b1, int s1,
                             const float* __restrict__ W2, const float* __restrict__ b2, int s2,
                             const float* __restrict__ W3, const float* __restrict__ b3,
                             float* __restrict__ C, int M, int N, int Kt, int Ks) {
    __shared__ float As[2][16][128];
    __shared__ float Ws[2][16][64];
    const int tid = threadIdx.x;
    const int tx = tid & 15, ty = tid >> 4;
    const int m0 = blockIdx.y * 128, n0 = blockIdx.x * 64;
    const int kbase = (SPLITK > 1) ? (int)blockIdx.z * Ks : 0;

    const float* Wb; const float* bb; int nW;
    if (n0 < s1)      { Wb = W1; bb = b1; nW = n0; }
    else if (n0 < s2) { Wb = W2; bb = b2; nW = n0 - s1; }
    else              { Wb = W3; bb = b3; nW = n0 - s2; }

    const bool useAdd = ADD && (n0 < NADD);

    unsigned long long acc[4][4];
    #pragma unroll
    for (int i = 0; i < 4; i++)
        #pragma unroll
        for (int j = 0; j < 4; j++) acc[i][j] = 0ull;

    const int r = tid >> 2, f = tid & 3;
    const float* Ap0 = A + (size_t)(m0 + r) * Kt + kbase + f * 4;
    const float* Ap1 = Ap0 + (size_t)64 * Kt;
    const float* A2p0 = nullptr; const float* A2p1 = nullptr;
    if (ADD) {
        A2p0 = A2 + (size_t)(m0 + r) * Kt + kbase + f * 4;
        A2p1 = A2p0 + (size_t)64 * Kt;
    }
    const float* Wp = Wb + (size_t)(nW + r) * Kt + kbase + f * 4;

    float4 a0, a1, w0;
    auto ldg = [&](int ko) {
        a0 = *(const float4*)(Ap0 + ko);
        a1 = *(const float4*)(Ap1 + ko);
        if (ADD && useAdd) {
            float4 e0 = *(const float4*)(A2p0 + ko);
            float4 e1 = *(const float4*)(A2p1 + ko);
            a0.x += e0.x; a0.y += e0.y; a0.z += e0.z; a0.w += e0.w;
            a1.x += e1.x; a1.y += e1.y; a1.z += e1.z; a1.w += e1.w;
        }
        w0 = *(const float4*)(Wp + ko);
    };
    auto stage = [&](int buf) {
        const int k4 = f * 4, sw = f << 3;
        As[buf][k4+0][r ^ sw] = a0.x; As[buf][k4+1][r ^ sw] = a0.y;
        As[buf][k4+2][r ^ sw] = a0.z; As[buf][k4+3][r ^ sw] = a0.w;
        As[buf][k4+0][(r+64) ^ sw] = a1.x; As[buf][k4+1][(r+64) ^ sw] = a1.y;
        As[buf][k4+2][(r+64) ^ sw] = a1.z; As[buf][k4+3][(r+64) ^ sw] = a1.w;
        Ws[buf][k4+0][r ^ sw] = w0.x; Ws[buf][k4+1][r ^ sw] = w0.y;
        Ws[buf][k4+2][r ^ sw] = w0.z; Ws[buf][k4+3][r ^ sw] = w0.w;
    };

    ldg(0);
    stage(0);
    __syncthreads();

    const int nit = Ks >> 4;
    const int ty8 = ty * 8, tx4 = tx * 4;
    for (int it = 0; it < nit; ++it) {
        const int buf = it & 1;
        if (it + 1 < nit) ldg((it + 1) << 4);
        #pragma unroll
        for (int k = 0; k < 16; k++) {
            const int sk = ((k >> 2) & 3) << 3;
            const float* ap = &As[buf][k][ty8 ^ sk];
            ulonglong2 aA = *(const ulonglong2*)ap;
            ulonglong2 aB = *(const ulonglong2*)(ap + 4);
            float4 bvv = *(const float4*)&Ws[buf][k][tx4 ^ sk];
            unsigned long long p0 = pack2(bvv.x), p1 = pack2(bvv.y),
                               p2 = pack2(bvv.z), p3 = pack2(bvv.w);
            fma2(acc[0][0], aA.x, p0); fma2(acc[0][1], aA.x, p1);
            fma2(acc[0][2], aA.x, p2); fma2(acc[0][3], aA.x, p3);
            fma2(acc[1][0], aA.y, p0); fma2(acc[1][1], aA.y, p1);
            fma2(acc[1][2], aA.y, p2); fma2(acc[1][3], aA.y, p3);
            fma2(acc[2][0], aB.x, p0); fma2(acc[2][1], aB.x, p1);
            fma2(acc[2][2], aB.x, p2); fma2(acc[2][3], aB.x, p3);
            fma2(acc[3][0], aB.y, p0); fma2(acc[3][1], aB.y, p1);
            fma2(acc[3][2], aB.y, p2); fma2(acc[3][3], aB.y, p3);
        }
        if (it + 1 < nit) stage(buf ^ 1);
        __syncthreads();
    }

    float bv[4] = {0.f, 0.f, 0.f, 0.f};
    if (SPLITK == 1 || blockIdx.z == 0) {
        const float4 bb4 = *(const float4*)&bb[nW + tx4];
        bv[0] = bb4.x; bv[1] = bb4.y; bv[2] = bb4.z; bv[3] = bb4.w;
    }
    float* Cz = C + (SPLITK > 1 ? (size_t)blockIdx.z * M * N : 0);
    #pragma unroll
    for (int j = 0; j < 4; j++) {
        const int n = n0 + tx4 + j;
        #pragma unroll
        for (int i = 0; i < 4; i++) {
            float2 v = unpack2(acc[i][j]);
            float o0 = v.x + bv[j], o1 = v.y + bv[j];
            if (RELU) { o0 = fmaxf(o0, 0.f); o1 = fmaxf(o1, 0.f); }
            const int m = m0 + ty8 + i * 2;
            Cz[(size_t)m * N + n]       = o0;
            Cz[(size_t)(m + 1) * N + n] = o1;
        }
    }
}

// ---------------- fused self-attention (flash, FFMA2, 2 queries/thread) ----------------
// qkv layout: [B*NQ, 768]: Q cols 0..255, K cols 256..511, V cols 512..767.
// grid = (NQ/32, H, B), block = 128.
__launch_bounds__(128)
__global__ void attn3_kernel(const float* __restrict__ qkv, float* __restrict__ out) {
    __shared__ float Ks[64][36];
    __shared__ float Vs[64][36];
    const int qt = blockIdx.x, h = blockIdx.y, b = blockIdx.z;
    const int tid = threadIdx.x;
    const int ql = tid >> 3, sub = tid & 7;
    const size_t qb = (size_t)b * NQ_ * 768 + h * HD_;
    const size_t ob = (size_t)b * NQ_ * D_ + h * HD_;
    const int qA = qt * 32 + ql;
    const int qB = qA + 16;
    const float* qrowA = qkv + qb + (size_t)qA * 768;
    const float* qrowB = qkv + qb + (size_t)qB * 768;

    unsigned long long q2a[16], q2b[16];
    #pragma unroll
    for (int p = 0; p < 8; p++) {
        ulonglong2 ta = *(const ulonglong2*)(qrowA + p * 4);
        ulonglong2 tb = *(const ulonglong2*)(qrowB + p * 4);
        q2a[2*p] = ta.x; q2a[2*p+1] = ta.y;
        q2b[2*p] = tb.x; q2b[2*p+1] = tb.y;
    }
    unsigned long long o2a[16], o2b[16];
    #pragma unroll
    for (int p = 0; p < 16; p++) { o2a[p] = 0ull; o2b[p] = 0ull; }

    const float scale = 0.17677669529663687f; // 1/sqrt(32)
    float mA = -1e30f, lA = 0.f;
    float mB = -1e30f, lB = 0.f;

    for (int kt = 0; kt < NQ_ / 64; kt++) {
        __syncthreads();
        #pragma unroll
        for (int i = 0; i < 4; i++) {
            int e = tid + i * 128;
            int kr = e >> 3, dc = (e & 7) * 4;
            const float* base = qkv + qb + (size_t)(kt * 64 + kr) * 768;
            *(float4*)&Ks[kr][dc] = *(const float4*)(base + 256 + dc);
            *(float4*)&Vs[kr][dc] = *(const float4*)(base + 512 + dc);
        }
        __syncthreads();

        float sA[8], sB[8];
        #pragma unroll
        for (int j = 0; j < 8; j++) {
            const float* kp = &Ks[j * 8 + sub][0];
            unsigned long long c0a = 0ull, c1a = 0ull, c0b = 0ull, c1b = 0ull;
            #pragma unroll
            for (int p = 0; p < 8; p++) {
                ulonglong2 kk = *(const ulonglong2*)(kp + p * 4);
                fma2(c0a, q2a[2*p],   kk.x);
                fma2(c1a, q2a[2*p+1], kk.y);
                fma2(c0b, q2b[2*p],   kk.x);
                fma2(c1b, q2b[2*p+1], kk.y);
            }
            float2 r0 = unpack2(c0a), r1 = unpack2(c1a);
            sA[j] = ((r0.x + r0.y) + (r1.x + r1.y)) * scale;
            float2 r2 = unpack2(c0b), r3 = unpack2(c1b);
            sB[j] = ((r2.x + r2.y) + (r3.x + r3.y)) * scale;
        }
        float tA = sA[0], tB = sB[0];
        #pragma unroll
        for (int j = 1; j < 8; j++) { tA = fmaxf(tA, sA[j]); tB = fmaxf(tB, sB[j]); }
        #pragma unroll
        for (int st = 1; st < 8; st <<= 1) {
            tA = fmaxf(tA, __shfl_xor_sync(0xffffffffu, tA, st));
            tB = fmaxf(tB, __shfl_xor_sync(0xffffffffu, tB, st));
        }

        const float mnA = fmaxf(mA, tA);
        const float crA = __expf(mA - mnA);
        mA = mnA; lA *= crA;
        const float mnB = fmaxf(mB, tB);
        const float crB = __expf(mB - mnB);
        mB = mnB; lB *= crB;
        const unsigned long long c2a = pack2(crA), c2b = pack2(crB);
        #pragma unroll
        for (int p = 0; p < 16; p++) { mul2(o2a[p], c2a); mul2(o2b[p], c2b); }

        float eA[8], eB[8];
        #pragma unroll
        for (int j = 0; j < 8; j++) {
            eA[j] = __expf(sA[j] - mA); lA += eA[j];
            eB[j] = __expf(sB[j] - mB); lB += eB[j];
        }
        #pragma unroll
        for (int j = 0; j < 8; j++) {
            const unsigned long long e2a = pack2(eA[j]);
            const unsigned long long e2b = pack2(eB[j]);
            const float* vp = &Vs[j * 8 + sub][0];
            #pragma unroll
            for (int p = 0; p < 8; p++) {
                ulonglong2 vv = *(const ulonglong2*)(vp + p * 4);
                fma2(o2a[2*p],   e2a, vv.x);
                fma2(o2a[2*p+1], e2a, vv.y);
                fma2(o2b[2*p],   e2b, vv.x);
                fma2(o2b[2*p+1], e2b, vv.y);
            }
        }
    }

    #pragma unroll
    for (int st = 1; st < 8; st <<= 1) {
        lA += __shfl_xor_sync(0xffffffffu, lA, st);
        lB += __shfl_xor_sync(0xffffffffu, lB, st);
        #pragma unroll
        for (int p = 0; p < 16; p++) {
            unsigned long long oa = __shfl_xor_sync(0xffffffffu, o2a[p], st);
            add2(o2a[p], oa);
            unsigned long long obv = __shfl_xor_sync(0xffffffffu, o2b[p], st);
            add2(o2b[p], obv);
        }
    }
    const unsigned long long iA = pack2(1.f / lA);
    const unsigned long long iB = pack2(1.f / lB);
    unsigned long long a0 = o2a[sub * 2], a1 = o2a[sub * 2 + 1];
    unsigned long long b0 = o2b[sub * 2], b1 = o2b[sub * 2 + 1];
    mul2(a0, iA); mul2(a1, iA);
    mul2(b0, iB); mul2(b1, iB);
    float2 ra0 = unpack2(a0), ra1 = unpack2(a1);
    float2 rb0 = unpack2(b0), rb1 = unpack2(b1);
    *(float4*)(out + ob + (size_t)qA * D_ + sub * 4) = make_float4(ra0.x, ra0.y, ra1.x, ra1.y);
    *(float4*)(out + ob + (size_t)qB * D_ + sub * 4) = make_float4(rb0.x, rb0.y, rb1.x, rb1.y);
}

// ---------------- MS deformable sampling (fused 16-wide softmax; NP offaw partials) ----
// grid = B*NQ, block = 256 (thread = h*32 + hd). val6: [MSRC, 1536], layer slice at col l*256.
template<int NP>
__global__ void msda_kernel(const float* __restrict__ val6, const float* __restrict__ offaw,
                            const float* __restrict__ refp, float* __restrict__ out, int l) {
    __shared__ float aw_s[128];
    __shared__ float off_s[256];
    const int bq = blockIdx.x;
    const int b = bq / NQ_;
    const int tid = threadIdx.x;
    const float* offp = offaw + (size_t)bq * 384;

    // sum split-K partials of the offsets into smem (256 values)
    {
        float v = 0.f;
        #pragma unroll
        for (int p = 0; p < NP; p++) v += offp[(size_t)p * MROWS_ * 384 + tid];
        off_s[tid] = v;
    }
    // fused softmax over each head's 16 logits (threads 0..127; 16-lane shfl groups)
    if (tid < 128) {
        float v = 0.f;
        #pragma unroll
        for (int p = 0; p < NP; p++) v += offp[(size_t)p * MROWS_ * 384 + 256 + tid];
        float mx = v;
        #pragma unroll
        for (int st = 1; st < 16; st <<= 1)
            mx = fmaxf(mx, __shfl_xor_sync(0xffffffffu, mx, st));
        const float e = __expf(v - mx);
        float s = e;
        #pragma unroll
        for (int st = 1; st < 16; st <<= 1)
            s += __shfl_xor_sync(0xffffffffu, s, st);
        aw_s[tid] = e / s;
    }
    __syncthreads();

    const int h = tid >> 5;
    const int hd = tid & 31;
    const float* rr = refp + (size_t)bq * 8;
    const float* vb = val6 + (size_t)b * STOT_ * VCOLS_ + l * D_ + h * HD_ + hd;
    float acc = 0.f;
    const int LVL_W[4]  = {64, 32, 16, 8};
    const int LVL_S0[4] = {0, 4096, 5120, 5376};
    #pragma unroll
    for (int lv = 0; lv < 4; lv++) {
        const int Wl = LVL_W[lv];
        const float Wf = (float)Wl;
        const int s0 = LVL_S0[lv];
        const float rx = rr[lv*2 + 0];
        const float ry = rr[lv*2 + 1];
        #pragma unroll
        for (int p = 0; p < 4; p++) {
            const int oi = (((h*4 + lv)*4) + p) * 2;
            const float locx = rx + off_s[oi + 0] / Wf;
            const float locy = ry + off_s[oi + 1] / Wf;   // H == W per level
            const float xx = locx * Wf - 0.5f;
            const float yy = locy * Wf - 0.5f;
            const float x0 = floorf(xx), y0 = floorf(yy);
            const float wx1 = xx - x0, wy1 = yy - y0;
            float sampv = 0.f;
            #pragma unroll
            for (int dy = 0; dy < 2; dy++) {
                const float yi = y0 + (float)dy;
                const float wy = dy ? wy1 : (1.f - wy1);
                #pragma unroll
                for (int dx = 0; dx < 2; dx++) {
                    const float xi = x0 + (float)dx;
                    const float wx = dx ? wx1 : (1.f - wx1);
                    const bool valid = (xi >= 0.f) && (xi <= Wf - 1.f) &&
                                       (yi >= 0.f) && (yi <= Wf - 1.f);
                    const float w = wx * wy * (valid ? 1.f : 0.f);
                    if (w != 0.f) {
                        const int xic = (int)fminf(fmaxf(xi, 0.f), Wf - 1.f);
                        const int yic = (int)fminf(fmaxf(yi, 0.f), Wf - 1.f);
                        const float g = vb[(size_t)(s0 + yic * Wl + xic) * VCOLS_];
                        sampv += g * w;
                    }
                }
            }
            acc += sampv * aw_s[h*16 + lv*4 + p];
        }
    }
    out[(size_t)bq * D_ + tid] = acc;
}

// ---------------- residual + layernorm: dst = LN(a + sum of NPART partials) ----------------
template<int NPART>
__global__ void ln_kernel(float* __restrict__ dst, const float* __restrict__ a,
                          const float* __restrict__ parts, const float* __restrict__ g,
                          const float* __restrict__ beta) {
    const int row = blockIdx.x;
    const int c = threadIdx.x;
    const size_t idx = (size_t)row * D_ + c;
    float v = a[idx];
    #pragma unroll
    for (int p = 0; p < NPART; p++) v += parts[(size_t)p * XSZ_ + idx];
    __shared__ float red[8];
    __shared__ float sh_mu, sh_var;
    float s = v;
    #pragma unroll
    for (int o = 16; o; o >>= 1) s += __shfl_xor_sync(0xffffffffu, s, o);
    if ((c & 31) == 0) red[c >> 5] = s;
    __syncthreads();
    if (c == 0) {
        float t = 0.f;
        #pragma unroll
        for (int i = 0; i < 8; i++) t += red[i];
        sh_mu = t * (1.f / 256.f);
    }
    __syncthreads();
    const float mu = sh_mu;
    const float d = v - mu;
    s = d * d;
    #pragma unroll
    for (int o = 16; o; o >>= 1) s += __shfl_xor_sync(0xffffffffu, s, o);
    if ((c & 31) == 0) red[c >> 5] = s;
    __syncthreads();
    if (c == 0) {
        float t = 0.f;
        #pragma unroll
        for (int i = 0; i < 8; i++) t += red[i];
        sh_var = t * (1.f / 256.f);
    }
    __syncthreads();
    const float y = d * rsqrtf(sh_var + 1e-5f) * g[c] + beta[c];
    dst[idx] = y;
}

// ---------------- host orchestration ----------------
extern "C" void kernel_launch(void* const* d_in, const int* in_sizes, int n_in,
                              void* d_out, int out_size) {
    (void)in_sizes; (void)n_in; (void)out_size;
    const float* tgt      = (const float*)d_in[0];
    const float* qpos     = (const float*)d_in[1];
    const float* refp     = (const float*)d_in[2];
    const float* src      = (const float*)d_in[3];
    const float* sa_w_q   = (const float*)d_in[4];
    const float* sa_b_q   = (const float*)d_in[5];
    const float* sa_w_k   = (const float*)d_in[6];
    const float* sa_b_k   = (const float*)d_in[7];
    const float* sa_w_v   = (const float*)d_in[8];
    const float* sa_b_v   = (const float*)d_in[9];
    const float* sa_w_o   = (const float*)d_in[10];
    const float* sa_b_o   = (const float*)d_in[11];
    const float* ln2_g    = (const float*)d_in[12];
    const float* ln2_b    = (const float*)d_in[13];
    const float* ca_w_off = (const float*)d_in[14];
    const float* ca_b_off = (const float*)d_in[15];
    const float* ca_w_attn= (const float*)d_in[16];
    const float* ca_b_attn= (const float*)d_in[17];
    const float* ca_w_val = (const float*)d_in[18];
    const float* ca_b_val = (const float*)d_in[19];
    const float* ca_w_out = (const float*)d_in[20];
    const float* ca_b_out = (const float*)d_in[21];
    const float* ln1_g    = (const float*)d_in[22];
    const float* ln1_b    = (const float*)d_in[23];
    const float* ffn_w1   = (const float*)d_in[24];
    const float* ffn_b1   = (const float*)d_in[25];
    const float* ffn_w2   = (const float*)d_in[26];
    const float* ffn_b2   = (const float*)d_in[27];
    const float* ln3_g    = (const float*)d_in[28];
    const float* ln3_b    = (const float*)d_in[29];

    float *x, *qkv, *t, *t2, *offaw, *val6, *ffn;
    cudaGetSymbolAddress((void**)&x,     g_x);
    cudaGetSymbolAddress((void**)&qkv,   g_qkv);
    cudaGetSymbolAddress((void**)&t,     g_t);
    cudaGetSymbolAddress((void**)&t2,    g_t2);
    cudaGetSymbolAddress((void**)&offaw, g_offaw);
    cudaGetSymbolAddress((void**)&val6,  g_val6);
    cudaGetSymbolAddress((void**)&ffn,   g_ffn);

    // one big value projection for all 6 layers: val6 = src @ ca_w_val^T + b  (N=1536)
    gemm4_kernel<false, false, 1><<<dim3(VCOLS_/64, MSRC_/128), 256>>>(
        src, nullptr, 0,
        ca_w_val, ca_b_val, VCOLS_, ca_w_val, ca_b_val, VCOLS_, ca_w_val, ca_b_val,
        val6, MSRC_, VCOLS_, D_, D_);

    const dim3 GQKV (768/64,   MROWS_/128);     // (12, 25) = 300 CTAs
    const dim3 GPROJ(D_/64,    MROWS_/128, 8);  // (4, 25, 8) = 800 CTAs, split-K8
    const dim3 GOA  (384/64,   MROWS_/128, 4);  // (6, 25, 4) = 600 CTAs, split-K4
    const dim3 GF1  (DFFN_/64, MROWS_/128);     // (16, 25) = 400 CTAs
    const dim3 GF2  (D_/64,    MROWS_/128, 8);  // (4, 25, 8) = 800 CTAs, split-K8
    const dim3 GATTN(NQ_/32, H_, B_);           // (50, 8, 2) = 800 CTAs

    for (int i = 0; i < NLAYERS_; i++) {
        const float* wq = sa_w_q + (size_t)i*D_*D_;   const float* bq = sa_b_q + i*D_;
        const float* wk = sa_w_k + (size_t)i*D_*D_;   const float* bk = sa_b_k + i*D_;
        const float* wv = sa_w_v + (size_t)i*D_*D_;   const float* bv = sa_b_v + i*D_;
        const float* wo = sa_w_o + (size_t)i*D_*D_;   const float* bo = sa_b_o + i*D_;
        const float* woff = ca_w_off + (size_t)i*D_*D_;     const float* boff = ca_b_off + i*D_;
        const float* watt = ca_w_attn + (size_t)i*128*D_;   const float* batt = ca_b_attn + i*128;
        const float* wco  = ca_w_out + (size_t)i*D_*D_;     const float* bco  = ca_b_out + i*D_;
        const float* w1 = ffn_w1 + (size_t)i*DFFN_*D_;      const float* b1 = ffn_b1 + i*DFFN_;
        const float* w2 = ffn_w2 + (size_t)i*D_*DFFN_;      const float* b2 = ffn_b2 + i*D_;

        const float* xin = (i == 0) ? tgt : x;

        // ---- self attention ----
        gemm4_kernel<false, true, 1><<<GQKV, 256>>>(
            xin, qpos, 512,
            wq, bq, 256, wk, bk, 512, wv, bv,
            qkv, MROWS_, 768, D_, D_);
        attn3_kernel<<<GATTN, 128>>>(qkv, t);
        // O-proj: split-K8 partials into t2[0..7]
        gemm4_kernel<false, false, 8><<<GPROJ, 256>>>(
            t, nullptr, 0,
            wo, bo, 256, wo, bo, 256, wo, bo,
            t2, MROWS_, D_, D_, D_/8);
        ln_kernel<8><<<MROWS_, 256>>>(x, xin, t2, ln2_g + i*D_, ln2_b + i*D_);

        // ---- deformable cross attention ----
        // offaw = (x+qpos) @ [w_off; w_attn]^T  (N=384, split-K4 partials)
        gemm4_kernel<false, true, 4><<<GOA, 256>>>(
            x, qpos, 384,
            woff, boff, 256, watt, batt, 384, watt, batt,
            offaw, MROWS_, 384, D_, D_/4);
        msda_kernel<4><<<MROWS_, 256>>>(val6, offaw, refp, t, i);
        gemm4_kernel<false, false, 8><<<GPROJ, 256>>>(
            t, nullptr, 0,
            wco, bco, 256, wco, bco, 256, wco, bco,
            t2, MROWS_, D_, D_, D_/8);
        ln_kernel<8><<<MROWS_, 256>>>(x, x, t2, ln1_g + i*D_, ln1_b + i*D_);

        // ---- FFN ----
        gemm4_kernel<true, false, 1><<<GF1, 256>>>(
            x, nullptr, 0,
            w1, b1, DFFN_, w1, b1, DFFN_, w1, b1,
            ffn, MROWS_, DFFN_, D_, D_);
        gemm4_kernel<false, false, 8><<<GF2, 256>>>(
            ffn, nullptr, 0,
            w2, b2, 256, w2, b2, 256, w2, b2,
            t2, MROWS_, D_, DFFN_, DFFN_/8);
        float* dst = (i == NLAYERS_ - 1) ? (float*)d_out : x;
        ln_kernel<8><<<MROWS_, 256>>>(dst, x, t2, ln3_g + i*D_, ln3_b + i*D_);
    }
}

// round 16
// speedup vs baseline: 1.2720x; 1.0498x over previous
#include <cuda_runtime.h>
#include <cuda_bf16.h>
#include <math.h>

// ---------------- problem constants ----------------
#define B_       2
#define NQ_      1600
#define D_       256
#define H_       8
#define HD_      32
#define DFFN_    1024
#define STOT_    5440
#define MROWS_   (B_*NQ_)          // 3200
#define MSRC_    (B_*STOT_)        // 10880
#define XSZ_     (MROWS_*D_)       // 819200
#define NLAYERS_ 6

// ---------------- device scratch (static, no allocation) ----------------
__device__ float g_x    [XSZ_];
__device__ float g_qkv  [MROWS_*768];
__device__ float g_t    [XSZ_];
__device__ float g_t2   [4*XSZ_];          // up to 4 split-K partials
__device__ float g_offaw[2*MROWS_*384];    // 2 split-K partials
__device__ float g_val6 [NLAYERS_*MSRC_*D_];  // per-layer contiguous [MSRC,256] blocks
__device__ float g_ffn  [MROWS_*DFFN_];

// ---------------- f32x2 packed-math helpers (sm_100+) ----------------
__device__ __forceinline__ unsigned long long pack2(float x) {
    unsigned long long r;
    unsigned int u = __float_as_uint(x);
    asm("mov.b64 %0, {%1, %1};" : "=l"(r) : "r"(u));
    return r;
}
__device__ __forceinline__ void fma2(unsigned long long& d, unsigned long long a, unsigned long long b) {
    asm("fma.rn.f32x2 %0, %1, %2, %0;" : "+l"(d) : "l"(a), "l"(b));
}
__device__ __forceinline__ void mul2(unsigned long long& d, unsigned long long a) {
    asm("mul.rn.f32x2 %0, %0, %1;" : "+l"(d) : "l"(a));
}
__device__ __forceinline__ void add2(unsigned long long& d, unsigned long long a) {
    asm("add.rn.f32x2 %0, %0, %1;" : "+l"(d) : "l"(a));
}
__device__ __forceinline__ float2 unpack2(unsigned long long v) {
    unsigned int lo, hi;
    asm("mov.b64 {%0, %1}, %2;" : "=r"(lo), "=r"(hi) : "l"(v));
    return make_float2(__uint_as_float(lo), __uint_as_float(hi));
}

// ---------------- GEMM: Cpart[z][M,N] = (A (+A2 on n<NADD)) * Wseg^T (+bias on z==0) ----
// Round-13 proven version. Tile 128x64, 256 threads, BK=16, FFMA2 8x4 micro-tile.
template<bool RELU, bool ADD, int SPLITK>
__launch_bounds__(256)
__global__ void gemm4_kernel(const float* __restrict__ A, const float* __restrict__ A2, int NADD,
                             const float* __restrict__ W1, const float* __restrict__ b1, int s1,
                             const float* __restrict__ W2, const float* __restrict__ b2, int s2,
                             const float* __restrict__ W3, const float* __restrict__ b3,
                             float* __restrict__ C, int M, int N, int Kt, int Ks) {
    __shared__ float As[2][16][128];
    __shared__ float Ws[2][16][64];
    const int tid = threadIdx.x;
    const int tx = tid & 15, ty = tid >> 4;
    const int m0 = blockIdx.y * 128, n0 = blockIdx.x * 64;
    const int kbase = (SPLITK > 1) ? (int)blockIdx.z * Ks : 0;

    const float* Wb; const float* bb; int nW;
    if (n0 < s1)      { Wb = W1; bb = b1; nW = n0; }
    else if (n0 < s2) { Wb = W2; bb = b2; nW = n0 - s1; }
    else              { Wb = W3; bb = b3; nW = n0 - s2; }

    const bool useAdd = ADD && (n0 < NADD);

    unsigned long long acc[4][4];
    #pragma unroll
    for (int i = 0; i < 4; i++)
        #pragma unroll
        for (int j = 0; j < 4; j++) acc[i][j] = 0ull;

    const int r = tid >> 2, f = tid & 3;
    const float* Ap0 = A + (size_t)(m0 + r) * Kt + kbase + f * 4;
    const float* Ap1 = Ap0 + (size_t)64 * Kt;
    const float* A2p0 = nullptr; const float* A2p1 = nullptr;
    if (ADD) {
        A2p0 = A2 + (size_t)(m0 + r) * Kt + kbase + f * 4;
        A2p1 = A2p0 + (size_t)64 * Kt;
    }
    const float* Wp = Wb + (size_t)(nW + r) * Kt + kbase + f * 4;

    float4 a0, a1, w0;
    auto ldg = [&](int ko) {
        a0 = *(const float4*)(Ap0 + ko);
        a1 = *(const float4*)(Ap1 + ko);
        if (ADD && useAdd) {
            float4 e0 = *(const float4*)(A2p0 + ko);
            float4 e1 = *(const float4*)(A2p1 + ko);
            a0.x += e0.x; a0.y += e0.y; a0.z += e0.z; a0.w += e0.w;
            a1.x += e1.x; a1.y += e1.y; a1.z += e1.z; a1.w += e1.w;
        }
        w0 = *(const float4*)(Wp + ko);
    };
    auto stage = [&](int buf) {
        const int k4 = f * 4, sw = f << 3;
        As[buf][k4+0][r ^ sw] = a0.x; As[buf][k4+1][r ^ sw] = a0.y;
        As[buf][k4+2][r ^ sw] = a0.z; As[buf][k4+3][r ^ sw] = a0.w;
        As[buf][k4+0][(r+64) ^ sw] = a1.x; As[buf][k4+1][(r+64) ^ sw] = a1.y;
        As[buf][k4+2][(r+64) ^ sw] = a1.z; As[buf][k4+3][(r+64) ^ sw] = a1.w;
        Ws[buf][k4+0][r ^ sw] = w0.x; Ws[buf][k4+1][r ^ sw] = w0.y;
        Ws[buf][k4+2][r ^ sw] = w0.z; Ws[buf][k4+3][r ^ sw] = w0.w;
    };

    ldg(0);
    stage(0);
    __syncthreads();

    const int nit = Ks >> 4;
    const int ty8 = ty * 8, tx4 = tx * 4;
    for (int it = 0; it < nit; ++it) {
        const int buf = it & 1;
        if (it + 1 < nit) ldg((it + 1) << 4);
        #pragma unroll
        for (int k = 0; k < 16; k++) {
            const int sk = ((k >> 2) & 3) << 3;
            const float* ap = &As[buf][k][ty8 ^ sk];
            ulonglong2 aA = *(const ulonglong2*)ap;
            ulonglong2 aB = *(const ulonglong2*)(ap + 4);
            float4 bvv = *(const float4*)&Ws[buf][k][tx4 ^ sk];
            unsigned long long p0 = pack2(bvv.x), p1 = pack2(bvv.y),
                               p2 = pack2(bvv.z), p3 = pack2(bvv.w);
            fma2(acc[0][0], aA.x, p0); fma2(acc[0][1], aA.x, p1);
            fma2(acc[0][2], aA.x, p2); fma2(acc[0][3], aA.x, p3);
            fma2(acc[1][0], aA.y, p0); fma2(acc[1][1], aA.y, p1);
            fma2(acc[1][2], aA.y, p2); fma2(acc[1][3], aA.y, p3);
            fma2(acc[2][0], aB.x, p0); fma2(acc[2][1], aB.x, p1);
            fma2(acc[2][2], aB.x, p2); fma2(acc[2][3], aB.x, p3);
            fma2(acc[3][0], aB.y, p0); fma2(acc[3][1], aB.y, p1);
            fma2(acc[3][2], aB.y, p2); fma2(acc[3][3], aB.y, p3);
        }
        if (it + 1 < nit) stage(buf ^ 1);
        __syncthreads();
    }

    float bv[4] = {0.f, 0.f, 0.f, 0.f};
    if (SPLITK == 1 || blockIdx.z == 0) {
        const float4 bb4 = *(const float4*)&bb[nW + tx4];
        bv[0] = bb4.x; bv[1] = bb4.y; bv[2] = bb4.z; bv[3] = bb4.w;
    }
    float* Cz = C + (SPLITK > 1 ? (size_t)blockIdx.z * M * N : 0);
    #pragma unroll
    for (int j = 0; j < 4; j++) {
        const int n = n0 + tx4 + j;
        #pragma unroll
        for (int i = 0; i < 4; i++) {
            float2 v = unpack2(acc[i][j]);
            float o0 = v.x + bv[j], o1 = v.y + bv[j];
            if (RELU) { o0 = fmaxf(o0, 0.f); o1 = fmaxf(o1, 0.f); }
            const int m = m0 + ty8 + i * 2;
            Cz[(size_t)m * N + n]       = o0;
            Cz[(size_t)(m + 1) * N + n] = o1;
        }
    }
}

// ---------------- fused self-attention (flash, FFMA2, 2 queries/thread) ----------------
__launch_bounds__(128)
__global__ void attn3_kernel(const float* __restrict__ qkv, float* __restrict__ out) {
    __shared__ float Ks[64][36];
    __shared__ float Vs[64][36];
    const int qt = blockIdx.x, h = blockIdx.y, b = blockIdx.z;
    const int tid = threadIdx.x;
    const int ql = tid >> 3, sub = tid & 7;
    const size_t qb = (size_t)b * NQ_ * 768 + h * HD_;
    const size_t ob = (size_t)b * NQ_ * D_ + h * HD_;
    const int qA = qt * 32 + ql;
    const int qB = qA + 16;
    const float* qrowA = qkv + qb + (size_t)qA * 768;
    const float* qrowB = qkv + qb + (size_t)qB * 768;

    unsigned long long q2a[16], q2b[16];
    #pragma unroll
    for (int p = 0; p < 8; p++) {
        ulonglong2 ta = *(const ulonglong2*)(qrowA + p * 4);
        ulonglong2 tb = *(const ulonglong2*)(qrowB + p * 4);
        q2a[2*p] = ta.x; q2a[2*p+1] = ta.y;
        q2b[2*p] = tb.x; q2b[2*p+1] = tb.y;
    }
    unsigned long long o2a[16], o2b[16];
    #pragma unroll
    for (int p = 0; p < 16; p++) { o2a[p] = 0ull; o2b[p] = 0ull; }

    const float scale = 0.17677669529663687f; // 1/sqrt(32)
    float mA = -1e30f, lA = 0.f;
    float mB = -1e30f, lB = 0.f;

    for (int kt = 0; kt < NQ_ / 64; kt++) {
        __syncthreads();
        #pragma unroll
        for (int i = 0; i < 4; i++) {
            int e = tid + i * 128;
            int kr = e >> 3, dc = (e & 7) * 4;
            const float* base = qkv + qb + (size_t)(kt * 64 + kr) * 768;
            *(float4*)&Ks[kr][dc] = *(const float4*)(base + 256 + dc);
            *(float4*)&Vs[kr][dc] = *(const float4*)(base + 512 + dc);
        }
        __syncthreads();

        float sA[8], sB[8];
        #pragma unroll
        for (int j = 0; j < 8; j++) {
            const float* kp = &Ks[j * 8 + sub][0];
            unsigned long long c0a = 0ull, c1a = 0ull, c0b = 0ull, c1b = 0ull;
            #pragma unroll
            for (int p = 0; p < 8; p++) {
                ulonglong2 kk = *(const ulonglong2*)(kp + p * 4);
                fma2(c0a, q2a[2*p],   kk.x);
                fma2(c1a, q2a[2*p+1], kk.y);
                fma2(c0b, q2b[2*p],   kk.x);
                fma2(c1b, q2b[2*p+1], kk.y);
            }
            float2 r0 = unpack2(c0a), r1 = unpack2(c1a);
            sA[j] = ((r0.x + r0.y) + (r1.x + r1.y)) * scale;
            float2 r2 = unpack2(c0b), r3 = unpack2(c1b);
            sB[j] = ((r2.x + r2.y) + (r3.x + r3.y)) * scale;
        }
        float tA = sA[0], tB = sB[0];
        #pragma unroll
        for (int j = 1; j < 8; j++) { tA = fmaxf(tA, sA[j]); tB = fmaxf(tB, sB[j]); }
        #pragma unroll
        for (int st = 1; st < 8; st <<= 1) {
            tA = fmaxf(tA, __shfl_xor_sync(0xffffffffu, tA, st));
            tB = fmaxf(tB, __shfl_xor_sync(0xffffffffu, tB, st));
        }

        const float mnA = fmaxf(mA, tA);
        const float crA = __expf(mA - mnA);
        mA = mnA; lA *= crA;
        const float mnB = fmaxf(mB, tB);
        const float crB = __expf(mB - mnB);
        mB = mnB; lB *= crB;
        const unsigned long long c2a = pack2(crA), c2b = pack2(crB);
        #pragma unroll
        for (int p = 0; p < 16; p++) { mul2(o2a[p], c2a); mul2(o2b[p], c2b); }

        float eA[8], eB[8];
        #pragma unroll
        for (int j = 0; j < 8; j++) {
            eA[j] = __expf(sA[j] - mA); lA += eA[j];
            eB[j] = __expf(sB[j] - mB); lB += eB[j];
        }
        #pragma unroll
        for (int j = 0; j < 8; j++) {
            const unsigned long long e2a = pack2(eA[j]);
            const unsigned long long e2b = pack2(eB[j]);
            const float* vp = &Vs[j * 8 + sub][0];
            #pragma unroll
            for (int p = 0; p < 8; p++) {
                ulonglong2 vv = *(const ulonglong2*)(vp + p * 4);
                fma2(o2a[2*p],   e2a, vv.x);
                fma2(o2a[2*p+1], e2a, vv.y);
                fma2(o2b[2*p],   e2b, vv.x);
                fma2(o2b[2*p+1], e2b, vv.y);
            }
        }
    }

    #pragma unroll
    for (int st = 1; st < 8; st <<= 1) {
        lA += __shfl_xor_sync(0xffffffffu, lA, st);
        lB += __shfl_xor_sync(0xffffffffu, lB, st);
        #pragma unroll
        for (int p = 0; p < 16; p++) {
            unsigned long long oa = __shfl_xor_sync(0xffffffffu, o2a[p], st);
            add2(o2a[p], oa);
            unsigned long long obv = __shfl_xor_sync(0xffffffffu, o2b[p], st);
            add2(o2b[p], obv);
        }
    }
    const unsigned long long iA = pack2(1.f / lA);
    const unsigned long long iB = pack2(1.f / lB);
    unsigned long long a0 = o2a[sub * 2], a1 = o2a[sub * 2 + 1];
    unsigned long long b0 = o2b[sub * 2], b1 = o2b[sub * 2 + 1];
    mul2(a0, iA); mul2(a1, iA);
    mul2(b0, iB); mul2(b1, iB);
    float2 ra0 = unpack2(a0), ra1 = unpack2(a1);
    float2 rb0 = unpack2(b0), rb1 = unpack2(b1);
    *(float4*)(out + ob + (size_t)qA * D_ + sub * 4) = make_float4(ra0.x, ra0.y, ra1.x, ra1.y);
    *(float4*)(out + ob + (size_t)qB * D_ + sub * 4) = make_float4(rb0.x, rb0.y, rb1.x, rb1.y);
}

// ---------------- MS deformable sampling (fused 16-wide softmax; NP offaw partials) ----
// val: this layer's [MSRC, 256] block. grid = B*NQ, block = 256.
template<int NP>
__global__ void msda_kernel(const float* __restrict__ val, const float* __restrict__ offaw,
                            const float* __restrict__ refp, float* __restrict__ out) {
    __shared__ float aw_s[128];
    __shared__ float off_s[256];
    const int bq = blockIdx.x;
    const int b = bq / NQ_;
    const int tid = threadIdx.x;
    const float* offp = offaw + (size_t)bq * 384;

    {
        float v = 0.f;
        #pragma unroll
        for (int p = 0; p < NP; p++) v += offp[(size_t)p * MROWS_ * 384 + tid];
        off_s[tid] = v;
    }
    if (tid < 128) {
        float v = 0.f;
        #pragma unroll
        for (int p = 0; p < NP; p++) v += offp[(size_t)p * MROWS_ * 384 + 256 + tid];
        float mx = v;
        #pragma unroll
        for (int st = 1; st < 16; st <<= 1)
            mx = fmaxf(mx, __shfl_xor_sync(0xffffffffu, mx, st));
        const float e = __expf(v - mx);
        float s = e;
        #pragma unroll
        for (int st = 1; st < 16; st <<= 1)
            s += __shfl_xor_sync(0xffffffffu, s, st);
        aw_s[tid] = e / s;
    }
    __syncthreads();

    const int h = tid >> 5;
    const int hd = tid & 31;
    const float* rr = refp + (size_t)bq * 8;
    const float* vb = val + (size_t)b * STOT_ * D_ + h * HD_ + hd;
    float acc = 0.f;
    const int LVL_W[4]  = {64, 32, 16, 8};
    const int LVL_S0[4] = {0, 4096, 5120, 5376};
    #pragma unroll
    for (int lv = 0; lv < 4; lv++) {
        const int Wl = LVL_W[lv];
        const float Wf = (float)Wl;
        const int s0 = LVL_S0[lv];
        const float rx = rr[lv*2 + 0];
        const float ry = rr[lv*2 + 1];
        #pragma unroll
        for (int p = 0; p < 4; p++) {
            const int oi = (((h*4 + lv)*4) + p) * 2;
            const float locx = rx + off_s[oi + 0] / Wf;
            const float locy = ry + off_s[oi + 1] / Wf;   // H == W per level
            const float xx = locx * Wf - 0.5f;
            const float yy = locy * Wf - 0.5f;
            const float x0 = floorf(xx), y0 = floorf(yy);
            const float wx1 = xx - x0, wy1 = yy - y0;
            float sampv = 0.f;
            #pragma unroll
            for (int dy = 0; dy < 2; dy++) {
                const float yi = y0 + (float)dy;
                const float wy = dy ? wy1 : (1.f - wy1);
                #pragma unroll
                for (int dx = 0; dx < 2; dx++) {
                    const float xi = x0 + (float)dx;
                    const float wx = dx ? wx1 : (1.f - wx1);
                    const bool valid = (xi >= 0.f) && (xi <= Wf - 1.f) &&
                                       (yi >= 0.f) && (yi <= Wf - 1.f);
                    const float w = wx * wy * (valid ? 1.f : 0.f);
                    if (w != 0.f) {
                        const int xic = (int)fminf(fmaxf(xi, 0.f), Wf - 1.f);
                        const int yic = (int)fminf(fmaxf(yi, 0.f), Wf - 1.f);
                        const float g = vb[(size_t)(s0 + yic * Wl + xic) * D_];
                        sampv += g * w;
                    }
                }
            }
            acc += sampv * aw_s[h*16 + lv*4 + p];
        }
    }
    out[(size_t)bq * D_ + tid] = acc;
}

// ---------------- residual + layernorm: dst = LN(a + sum of NPART partials) ----------------
template<int NPART>
__global__ void ln_kernel(float* __restrict__ dst, const float* __restrict__ a,
                          const float* __restrict__ parts, const float* __restrict__ g,
                          const float* __restrict__ beta) {
    const int row = blockIdx.x;
    const int c = threadIdx.x;
    const size_t idx = (size_t)row * D_ + c;
    float v = a[idx];
    #pragma unroll
    for (int p = 0; p < NPART; p++) v += parts[(size_t)p * XSZ_ + idx];
    __shared__ float red[8];
    __shared__ float sh_mu, sh_var;
    float s = v;
    #pragma unroll
    for (int o = 16; o; o >>= 1) s += __shfl_xor_sync(0xffffffffu, s, o);
    if ((c & 31) == 0) red[c >> 5] = s;
    __syncthreads();
    if (c == 0) {
        float t = 0.f;
        #pragma unroll
        for (int i = 0; i < 8; i++) t += red[i];
        sh_mu = t * (1.f / 256.f);
    }
    __syncthreads();
    const float mu = sh_mu;
    const float d = v - mu;
    s = d * d;
    #pragma unroll
    for (int o = 16; o; o >>= 1) s += __shfl_xor_sync(0xffffffffu, s, o);
    if ((c & 31) == 0) red[c >> 5] = s;
    __syncthreads();
    if (c == 0) {
        float t = 0.f;
        #pragma unroll
        for (int i = 0; i < 8; i++) t += red[i];
        sh_var = t * (1.f / 256.f);
    }
    __syncthreads();
    const float y = d * rsqrtf(sh_var + 1e-5f) * g[c] + beta[c];
    dst[idx] = y;
}

// ---------------- host orchestration ----------------
extern "C" void kernel_launch(void* const* d_in, const int* in_sizes, int n_in,
                              void* d_out, int out_size) {
    (void)in_sizes; (void)n_in; (void)out_size;
    const float* tgt      = (const float*)d_in[0];
    const float* qpos     = (const float*)d_in[1];
    const float* refp     = (const float*)d_in[2];
    const float* src      = (const float*)d_in[3];
    const float* sa_w_q   = (const float*)d_in[4];
    const float* sa_b_q   = (const float*)d_in[5];
    const float* sa_w_k   = (const float*)d_in[6];
    const float* sa_b_k   = (const float*)d_in[7];
    const float* sa_w_v   = (const float*)d_in[8];
    const float* sa_b_v   = (const float*)d_in[9];
    const float* sa_w_o   = (const float*)d_in[10];
    const float* sa_b_o   = (const float*)d_in[11];
    const float* ln2_g    = (const float*)d_in[12];
    const float* ln2_b    = (const float*)d_in[13];
    const float* ca_w_off = (const float*)d_in[14];
    const float* ca_b_off = (const float*)d_in[15];
    const float* ca_w_attn= (const float*)d_in[16];
    const float* ca_b_attn= (const float*)d_in[17];
    const float* ca_w_val = (const float*)d_in[18];
    const float* ca_b_val = (const float*)d_in[19];
    const float* ca_w_out = (const float*)d_in[20];
    const float* ca_b_out = (const float*)d_in[21];
    const float* ln1_g    = (const float*)d_in[22];
    const float* ln1_b    = (const float*)d_in[23];
    const float* ffn_w1   = (const float*)d_in[24];
    const float* ffn_b1   = (const float*)d_in[25];
    const float* ffn_w2   = (const float*)d_in[26];
    const float* ffn_b2   = (const float*)d_in[27];
    const float* ln3_g    = (const float*)d_in[28];
    const float* ln3_b    = (const float*)d_in[29];

    float *x, *qkv, *t, *t2, *offaw, *val6, *ffn;
    cudaGetSymbolAddress((void**)&x,     g_x);
    cudaGetSymbolAddress((void**)&qkv,   g_qkv);
    cudaGetSymbolAddress((void**)&t,     g_t);
    cudaGetSymbolAddress((void**)&t2,    g_t2);
    cudaGetSymbolAddress((void**)&offaw, g_offaw);
    cudaGetSymbolAddress((void**)&val6,  g_val6);
    cudaGetSymbolAddress((void**)&ffn,   g_ffn);

    // side stream + events for overlapping the value projections (created once,
    // outside any graph capture — first call is the uncaptured correctness run)
    static cudaStream_t s2 = nullptr;
    static cudaEvent_t evFork;
    static cudaEvent_t evVal[NLAYERS_];
    if (s2 == nullptr) {
        cudaStreamCreateWithFlags(&s2, cudaStreamNonBlocking);
        cudaEventCreateWithFlags(&evFork, cudaEventDisableTiming);
        for (int l = 0; l < NLAYERS_; l++)
            cudaEventCreateWithFlags(&evVal[l], cudaEventDisableTiming);
    }

    const dim3 GQKV (768/64,   MROWS_/128);     // 300 CTAs
    const dim3 GPROJ(D_/64,    MROWS_/128, 4);  // 400 CTAs, split-K4
    const dim3 GOA  (384/64,   MROWS_/128, 2);  // 300 CTAs, split-K2
    const dim3 GF1  (DFFN_/64, MROWS_/128);     // 400 CTAs
    const dim3 GF2  (D_/64,    MROWS_/128, 4);  // 400 CTAs, split-K4
    const dim3 GVAL (D_/64,    MSRC_/128);      // 340 CTAs
    const dim3 GATTN(NQ_/32, H_, B_);           // 800 CTAs

    // fork: per-layer value projections run on s2, joined right before each msda
    cudaEventRecord(evFork, 0);                 // legacy default stream (capture stream)
    cudaStreamWaitEvent(s2, evFork, 0);
    for (int l = 0; l < NLAYERS_; l++) {
        const float* wval = ca_w_val + (size_t)l*D_*D_;
        const float* bval = ca_b_val + l*D_;
        gemm4_kernel<false, false, 1><<<GVAL, 256, 0, s2>>>(
            src, nullptr, 0,
            wval, bval, D_, wval, bval, D_, wval, bval,
            val6 + (size_t)l*MSRC_*D_, MSRC_, D_, D_, D_);
        cudaEventRecord(evVal[l], s2);
    }

    for (int i = 0; i < NLAYERS_; i++) {
        const float* wq = sa_w_q + (size_t)i*D_*D_;   const float* bq = sa_b_q + i*D_;
        const float* wk = sa_w_k + (size_t)i*D_*D_;   const float* bk = sa_b_k + i*D_;
        const float* wv = sa_w_v + (size_t)i*D_*D_;   const float* bv = sa_b_v + i*D_;
        const float* wo = sa_w_o + (size_t)i*D_*D_;   const float* bo = sa_b_o + i*D_;
        const float* woff = ca_w_off + (size_t)i*D_*D_;     const float* boff = ca_b_off + i*D_;
        const float* watt = ca_w_attn + (size_t)i*128*D_;   const float* batt = ca_b_attn + i*128;
        const float* wco  = ca_w_out + (size_t)i*D_*D_;     const float* bco  = ca_b_out + i*D_;
        const float* w1 = ffn_w1 + (size_t)i*DFFN_*D_;      const float* b1 = ffn_b1 + i*DFFN_;
        const float* w2 = ffn_w2 + (size_t)i*D_*DFFN_;      const float* b2 = ffn_b2 + i*D_;

        const float* xin = (i == 0) ? tgt : x;

        // ---- self attention ----
        gemm4_kernel<false, true, 1><<<GQKV, 256>>>(
            xin, qpos, 512,
            wq, bq, 256, wk, bk, 512, wv, bv,
            qkv, MROWS_, 768, D_, D_);
        attn3_kernel<<<GATTN, 128>>>(qkv, t);
        gemm4_kernel<false, false, 4><<<GPROJ, 256>>>(
            t, nullptr, 0,
            wo, bo, 256, wo, bo, 256, wo, bo,
            t2, MROWS_, D_, D_, D_/4);
        ln_kernel<4><<<MROWS_, 256>>>(x, xin, t2, ln2_g + i*D_, ln2_b + i*D_);

        // ---- deformable cross attention ----
        gemm4_kernel<false, true, 2><<<GOA, 256>>>(
            x, qpos, 384,
            woff, boff, 256, watt, batt, 384, watt, batt,
            offaw, MROWS_, 384, D_, D_/2);
        cudaStreamWaitEvent(0, evVal[i], 0);    // join: layer-i value slice ready
        msda_kernel<2><<<MROWS_, 256>>>(val6 + (size_t)i*MSRC_*D_, offaw, refp, t);
        gemm4_kernel<false, false, 4><<<GPROJ, 256>>>(
            t, nullptr, 0,
            wco, bco, 256, wco, bco, 256, wco, bco,
            t2, MROWS_, D_, D_, D_/4);
        ln_kernel<4><<<MROWS_, 256>>>(x, x, t2, ln1_g + i*D_, ln1_b + i*D_);

        // ---- FFN ----
        gemm4_kernel<true, false, 1><<<GF1, 256>>>(
            x, nullptr, 0,
            w1, b1, DFFN_, w1, b1, DFFN_, w1, b1,
            ffn, MROWS_, DFFN_, D_, D_);
        gemm4_kernel<false, false, 4><<<GF2, 256>>>(
            ffn, nullptr, 0,
            w2, b2, 256, w2, b2, 256, w2, b2,
            t2, MROWS_, D_, DFFN_, DFFN_/4);
        float* dst = (i == NLAYERS_ - 1) ? (float*)d_out : x;
        ln_kernel<4><<<MROWS_, 256>>>(dst, x, t2, ln3_g + i*D_, ln3_b + i*D_);
    }
}